// round 15
// baseline (speedup 1.0000x reference)
#include <cuda_runtime.h>
#include <cuda_fp16.h>
#include <cstdint>

#define NN 100000
#define NE 300000
#define MT 10000

typedef unsigned long long u64;
typedef unsigned int u32;

// ---------------- scratch (device globals; no allocation allowed) ----------------
__device__ __half g_nh     [(size_t)NN*256];   // node_h fp16
__device__ __half g_base   [(size_t)NE*256];   // fp16 intermediate
__device__ __half g_y      [(size_t)NE*256];   // fp16 intermediate
__device__ float  g_aggA   [(size_t)NN*256];
__device__ float  g_aggB   [(size_t)NN*256];
__device__ float  g_nodesum[(size_t)NN*256];
// single-fp16 A-side buffers
__device__ __half g_fn[(size_t)NN*256];
__device__ __half g_fe[(size_t)NE*64];
__device__ __half g_tm[(size_t)MT*256];
__device__ __half g_a [(size_t)NE*256];
__device__ __half g_ns[(size_t)NN*256];
// B matrices transposed, single fp16: B[n][k] = W[k][n]
__device__ __half g_B1[256*256];
__device__ __half g_B2[256*64];
__device__ __half g_B3[256*256];
__device__ __half g_B4[256*256];
__device__ __half g_B5[256*256];

// ---------------- helpers ----------------
__device__ __forceinline__ u32 smem_u32(const void* p) {
    u32 a; asm("{ .reg .u64 t; cvta.to.shared.u64 t, %1; cvt.u32.u64 %0, t; }" : "=r"(a) : "l"(p));
    return a;
}
__device__ __forceinline__ void cp16(u32 dst, const void* src) {
    asm volatile("cp.async.cg.shared.global [%0], [%1], 16;" :: "r"(dst), "l"(src));
}
__device__ __forceinline__ void red2(float* p, float a, float b) {
    asm volatile("red.global.add.v2.f32 [%0], {%1,%2};" :: "l"(p), "f"(a), "f"(b) : "memory");
}
__device__ __forceinline__ void red4(float* p, float a, float b, float c, float d) {
    asm volatile("red.global.add.v4.f32 [%0], {%1,%2,%3,%4};"
                 :: "l"(p), "f"(a), "f"(b), "f"(c), "f"(d) : "memory");
}
__device__ __forceinline__ void ldsm4(u32* r, u32 addr) {
    asm volatile("ldmatrix.sync.aligned.m8n8.x4.shared.b16 {%0,%1,%2,%3}, [%4];"
                 : "=r"(r[0]), "=r"(r[1]), "=r"(r[2]), "=r"(r[3]) : "r"(addr));
}
__device__ __forceinline__ void mma16816(float* d, const u32* a, const u32* b) {
    asm volatile("mma.sync.aligned.m16n8k16.row.col.f32.f16.f16.f32 "
                 "{%0,%1,%2,%3}, {%4,%5,%6,%7}, {%8,%9}, {%0,%1,%2,%3};"
                 : "+f"(d[0]), "+f"(d[1]), "+f"(d[2]), "+f"(d[3])
                 : "r"(a[0]), "r"(a[1]), "r"(a[2]), "r"(a[3]), "r"(b[0]), "r"(b[1]));
}
__device__ __forceinline__ u32 pack2(float x, float y) {
    __half2 h = __floats2half2_rn(x, y);
    return *(u32*)&h;
}
__device__ __forceinline__ float2 unpack2(u32 v) {
    __half2 h = *(__half2*)&v;
    return make_float2(__half2float(__low2half(h)), __half2float(__high2half(h)));
}
__device__ __forceinline__ void conv_store4(__half* hp, float4 v) {
    ((u32*)hp)[0] = pack2(v.x, v.y);
    ((u32*)hp)[1] = pack2(v.z, v.w);
}

// smem: 2 stages x [A | B], each buffer 128 rows x 144 bytes (128 data + 16 pad)
#define ROWB 144u
#define BUF_BYTES (128u * ROWB)          // 18432
#define STAGE_BYTES (2u * BUF_BYTES)     // 36864
#define SM_BYTES (2 * STAGE_BYTES)       // 73728 -> 2 CTAs/SM

// ------------------- mma.sync GEMM: C[M,256] = A[M,K] @ W[K,256], BK=64 -------------------
// single fp16 term, fp32 accumulate. CTA tile 128x128, grid (2, tiles_m).
// MODE 0: hC(f16) = acc                                       (node_h)
// MODE 1: hC(f16) = acc + addmatH[gidx[r]] + bias ; rout = relu (fp16)
// MODE 2: hC[gidx[r]](f16) += acc ; rout patched
// MODE 3: hC(f16) = acc ; red agg[gidx[r]] += acc
// MODE 6: C(f32) = relu(A@B + A2@B2 + bias)                   (fused readout; 8 chunks)
template<int MODE>
__global__ __launch_bounds__(256, 2)
void tgemm(const __half* __restrict__ A, const __half* __restrict__ B,
           const __half* __restrict__ A2, const __half* __restrict__ B2,
           float* __restrict__ C, __half* __restrict__ hC, int M, int K,
           const float* __restrict__ bias, const __half* __restrict__ addmatH,
           const int* __restrict__ gidx, float* __restrict__ agg,
           __half* __restrict__ rout)
{
    extern __shared__ char smem[];
    const u32 sb = smem_u32(smem);
    const int tid  = threadIdx.x;
    const int lane = tid & 31, w = tid >> 5;
    const int wm = w >> 2, wn = w & 3;
    const int bm = blockIdx.y * 128;
    const int bn = blockIdx.x * 128;
    const int nchunks = (MODE == 6) ? 8 : (K >> 6);

    float acc[4][4][4];
    #pragma unroll
    for (int i = 0; i < 4; i++)
        #pragma unroll
        for (int j = 0; j < 4; j++)
            #pragma unroll
            for (int q = 0; q < 4; q++) acc[i][j][q] = 0.f;

    const int lr = tid >> 1;           // smem row 0..127
    const int hh = tid & 1;            // row half (64 bytes each)
    int growA = bm + lr; if (growA >= M) growA = M - 1;
    const u32 so = (u32)lr * ROWB + (u32)hh * 64u;

    auto load_chunk = [&](int c, int s) {
        const __half *pA = A, *pB = B;
        int cc = c;
        if (MODE == 6 && c >= 4) { pA = A2; pB = B2; cc = c - 4; }
        const u32 base = sb + (u32)s * STAGE_BYTES;
        const size_t gbA = ((size_t)growA * K + cc * 64 + hh * 32) * 2;
        const size_t gbB = ((size_t)(bn + lr) * K + cc * 64 + hh * 32) * 2;
        #pragma unroll
        for (int q = 0; q < 4; q++) {
            cp16(base + so + q * 16u,             (const char*)pA + gbA + q * 16);
            cp16(base + BUF_BYTES + so + q * 16u, (const char*)pB + gbB + q * 16);
        }
    };

    const u32 aAddr = (u32)(wm * 64 + (lane & 15)) * ROWB + (u32)(lane >> 4) * 16u;
    const u32 bAddr = (u32)(wn * 32 + ((lane >> 4) << 3) + (lane & 7)) * ROWB
                    + (u32)((lane >> 3) & 1) * 16u;

    load_chunk(0, 0);
    asm volatile("cp.async.commit_group;" ::: "memory");

    for (int c = 0; c < nchunks; c++) {
        const int s = c & 1;
        if (c + 1 < nchunks) {
            load_chunk(c + 1, (c + 1) & 1);
            asm volatile("cp.async.commit_group;" ::: "memory");
            asm volatile("cp.async.wait_group 1;" ::: "memory");
        } else {
            asm volatile("cp.async.wait_group 0;" ::: "memory");
        }
        __syncthreads();

        const u32 stage = sb + (u32)s * STAGE_BYTES;
        #pragma unroll
        for (int ks = 0; ks < 4; ks++) {
            u32 bfv[2][4];
            #pragma unroll
            for (int p = 0; p < 2; p++)
                ldsm4(bfv[p], stage + BUF_BYTES + bAddr + (u32)p * (16u * ROWB) + (u32)ks * 32u);
            u32 af[4][4];
            #pragma unroll
            for (int mt = 0; mt < 4; mt++)
                ldsm4(af[mt], stage + aAddr + (u32)mt * (16u * ROWB) + (u32)ks * 32u);
            #pragma unroll
            for (int mt = 0; mt < 4; mt++)
                #pragma unroll
                for (int nt = 0; nt < 4; nt++)
                    mma16816(acc[mt][nt], af[mt], &bfv[nt >> 1][(nt & 1) * 2]);
        }
        __syncthreads();
    }

    // ---------------- epilogue ----------------
    #pragma unroll
    for (int mt = 0; mt < 4; mt++) {
        #pragma unroll
        for (int half = 0; half < 2; half++) {
            const int r = bm + wm * 64 + mt * 16 + (lane >> 2) + half * 8;
            if (r >= M) continue;
            int g = 0;
            if (MODE == 1 || MODE == 2 || MODE == 3) g = __ldg(gidx + r);
            const size_t rowC = (size_t)r * 256;
            #pragma unroll
            for (int nt = 0; nt < 4; nt++) {
                const int c0 = bn + wn * 32 + nt * 8 + (lane & 3) * 2;
                float vx = acc[mt][nt][2 * half], vy = acc[mt][nt][2 * half + 1];
                if constexpr (MODE == 0) {
                    *(u32*)(hC + rowC + c0) = pack2(vx, vy);
                } else if constexpr (MODE == 1) {
                    const float2 ad = unpack2(*(const u32*)(addmatH + (size_t)g * 256 + c0));
                    const float2 bi = *(const float2*)(bias + c0);
                    vx += ad.x + bi.x; vy += ad.y + bi.y;
                    *(u32*)(hC + rowC + c0)   = pack2(vx, vy);
                    *(u32*)(rout + rowC + c0) = pack2(fmaxf(vx, 0.f), fmaxf(vy, 0.f));
                } else if constexpr (MODE == 2) {
                    const size_t rowG = (size_t)g * 256;
                    float2 bs = unpack2(*(u32*)(hC + rowG + c0));
                    bs.x += vx; bs.y += vy;
                    *(u32*)(hC + rowG + c0)   = pack2(bs.x, bs.y);
                    *(u32*)(rout + rowG + c0) = pack2(fmaxf(bs.x, 0.f), fmaxf(bs.y, 0.f));
                } else if constexpr (MODE == 3) {
                    *(u32*)(hC + rowC + c0) = pack2(vx, vy);
                    red2(agg + (size_t)g * 256 + c0, vx, vy);
                } else if constexpr (MODE == 6) {
                    const float2 bi = *(const float2*)(bias + c0);
                    *(float2*)(C + rowC + c0) =
                        make_float2(fmaxf(vx + bi.x, 0.f), fmaxf(vy + bi.y, 0.f));
                }
            }
        }
    }
}

// ---------------- fused prologue: zeros + input conversions + weight transposes ----------
#define PR_Z  (3 * NN * 64)
#define PR_FN (NN * 64)
#define PR_FE (NE * 16)
#define PR_TM (MT * 64)
#define PR_BULK (PR_Z + PR_FN + PR_FE + PR_TM)
#define PR_W  (65536 * 4 + 16384)
#define PR_TOTAL (PR_BULK + PR_W)

__global__ __launch_bounds__(256)
void prologue_k(const float* __restrict__ f_node, const float* __restrict__ f_edge,
                const float* __restrict__ tree_msg,
                const float* __restrict__ W1, const float* __restrict__ W2,
                const float* __restrict__ W3, const float* __restrict__ W4,
                const float* __restrict__ W5)
{
    int i = blockIdx.x * blockDim.x + threadIdx.x;
    if (i >= PR_TOTAL) return;
    if (i < PR_Z) {
        int j = i;
        float4* p;
        if (j < NN * 64) p = (float4*)g_aggA;
        else if (j < 2 * NN * 64) { p = (float4*)g_aggB; j -= NN * 64; }
        else { p = (float4*)g_nodesum; j -= 2 * NN * 64; }
        p[j] = make_float4(0.f, 0.f, 0.f, 0.f);
        return;
    }
    i -= PR_Z;
    if (i < PR_FN) {
        conv_store4(g_fn + (size_t)i * 4, ((const float4*)f_node)[i]);
        return;
    }
    i -= PR_FN;
    if (i < PR_FE) {
        conv_store4(g_fe + (size_t)i * 4, ((const float4*)f_edge)[i]);
        return;
    }
    i -= PR_FE;
    if (i < PR_TM) {
        conv_store4(g_tm + (size_t)i * 4, ((const float4*)tree_msg)[i]);
        return;
    }
    i -= PR_TM;
    const float* W; __half* h; int K;
    if (i < 65536)                { W = W1; h = g_B1; K = 256; }
    else if (i < 65536 + 16384)   { i -= 65536; W = W2; h = g_B2; K = 64; }
    else if (i < 2*65536 + 16384) { i -= 65536 + 16384; W = W3; h = g_B3; K = 256; }
    else if (i < 3*65536 + 16384) { i -= 2*65536 + 16384; W = W4; h = g_B4; K = 256; }
    else                          { i -= 3*65536 + 16384; W = W5; h = g_B5; K = 256; }
    int n = i / K, k = i % K;
    h[i] = __float2half_rn(W[(size_t)k * 256 + n]);
}

// ---------------- combine: m = relu(base + agg[src] - y[e^1]), 8 lanes/thread --------
template<bool FINAL>
__global__ __launch_bounds__(256)
void combine_k(const __half* __restrict__ base, const float* __restrict__ agg,
               const __half* __restrict__ y, const int* __restrict__ esrc,
               const int* __restrict__ edst,
               __half* __restrict__ mOut, float* __restrict__ nodesum)
{
    int gid = blockIdx.x * blockDim.x + threadIdx.x;
    if (gid >= NE * 32) return;
    int e = gid >> 5;
    int c = (gid & 31) << 3;
    int s = __ldg(esrc + e);
    uint4 bv = *(const uint4*)(base + (size_t)e * 256 + c);
    uint4 yv = *(const uint4*)(y + (size_t)(e ^ 1) * 256 + c);
    const float4* ap = (const float4*)(agg + (size_t)s * 256 + c);
    float4 a0 = ap[0], a1 = ap[1];
    float2 b0 = unpack2(bv.x), b1 = unpack2(bv.y), b2 = unpack2(bv.z), b3 = unpack2(bv.w);
    float2 z0 = unpack2(yv.x), z1 = unpack2(yv.y), z2 = unpack2(yv.z), z3 = unpack2(yv.w);
    float m0 = fmaxf(b0.x + a0.x - z0.x, 0.f);
    float m1 = fmaxf(b0.y + a0.y - z0.y, 0.f);
    float m2 = fmaxf(b1.x + a0.z - z1.x, 0.f);
    float m3 = fmaxf(b1.y + a0.w - z1.y, 0.f);
    float m4 = fmaxf(b2.x + a1.x - z2.x, 0.f);
    float m5 = fmaxf(b2.y + a1.y - z2.y, 0.f);
    float m6 = fmaxf(b3.x + a1.z - z3.x, 0.f);
    float m7 = fmaxf(b3.y + a1.w - z3.y, 0.f);
    if (FINAL) {
        int d = __ldg(edst + e);
        float* np = nodesum + (size_t)d * 256 + c;
        red4(np,     m0, m1, m2, m3);
        red4(np + 4, m4, m5, m6, m7);
    } else {
        uint4 hv;
        hv.x = pack2(m0, m1); hv.y = pack2(m2, m3);
        hv.z = pack2(m4, m5); hv.w = pack2(m6, m7);
        *(uint4*)(mOut + (size_t)e * 256 + c) = hv;
    }
}

// convert nodesum -> fp16, 8 elems/thread
__global__ void conv_k(const float* __restrict__ x, __half* __restrict__ h, int n8)
{
    int i = blockIdx.x * blockDim.x + threadIdx.x;
    if (i >= n8) return;
    const float4* xp = (const float4*)(x + (size_t)i * 8);
    float4 v0 = xp[0], v1 = xp[1];
    uint4 hv;
    hv.x = pack2(v0.x, v0.y); hv.y = pack2(v0.z, v0.w);
    hv.z = pack2(v1.x, v1.y); hv.w = pack2(v1.z, v1.w);
    *(uint4*)(h + (size_t)i * 8) = hv;
}

// --------------------------------- launch ---------------------------------
extern "C" void kernel_launch(void* const* d_in, const int* in_sizes, int n_in,
                              void* d_out, int out_size)
{
    const float* f_node   = (const float*)d_in[0];
    const float* f_edge   = (const float*)d_in[1];
    const float* tree_msg = (const float*)d_in[2];
    const float* W1       = (const float*)d_in[3];
    const float* W2       = (const float*)d_in[4];
    const float* W3       = (const float*)d_in[5];
    const float* b1       = (const float*)d_in[6];
    const float* W4       = (const float*)d_in[7];
    const float* W5       = (const float*)d_in[8];
    const float* b2       = (const float*)d_in[9];
    const int* edge_src   = (const int*)d_in[10];
    const int* edge_dst   = (const int*)d_in[11];
    const int* tree_tgt   = (const int*)d_in[12];
    float* out = (float*)d_out;

    float *aggA, *aggB, *nodesum;
    __half *nh, *base, *y, *fn, *fe, *tm, *am, *ns, *B1, *B2, *B3, *B4, *B5;
    cudaGetSymbolAddress((void**)&nh,      g_nh);
    cudaGetSymbolAddress((void**)&base,    g_base);
    cudaGetSymbolAddress((void**)&y,       g_y);
    cudaGetSymbolAddress((void**)&aggA,    g_aggA);
    cudaGetSymbolAddress((void**)&aggB,    g_aggB);
    cudaGetSymbolAddress((void**)&nodesum, g_nodesum);
    cudaGetSymbolAddress((void**)&fn, g_fn);
    cudaGetSymbolAddress((void**)&fe, g_fe);
    cudaGetSymbolAddress((void**)&tm, g_tm);
    cudaGetSymbolAddress((void**)&am, g_a);
    cudaGetSymbolAddress((void**)&ns, g_ns);
    cudaGetSymbolAddress((void**)&B1, g_B1);
    cudaGetSymbolAddress((void**)&B2, g_B2);
    cudaGetSymbolAddress((void**)&B3, g_B3);
    cudaGetSymbolAddress((void**)&B4, g_B4);
    cudaGetSymbolAddress((void**)&B5, g_B5);

    cudaFuncSetAttribute(tgemm<0>, cudaFuncAttributeMaxDynamicSharedMemorySize, SM_BYTES);
    cudaFuncSetAttribute(tgemm<1>, cudaFuncAttributeMaxDynamicSharedMemorySize, SM_BYTES);
    cudaFuncSetAttribute(tgemm<2>, cudaFuncAttributeMaxDynamicSharedMemorySize, SM_BYTES);
    cudaFuncSetAttribute(tgemm<3>, cudaFuncAttributeMaxDynamicSharedMemorySize, SM_BYTES);
    cudaFuncSetAttribute(tgemm<6>, cudaFuncAttributeMaxDynamicSharedMemorySize, SM_BYTES);

    const dim3 blk(256);
    const int combGrid = (NE * 32 + 255) / 256;
    const dim3 gN(2, (NN + 127) / 128);
    const dim3 gE(2, (NE + 127) / 128);
    const dim3 gT(2, (MT + 127) / 128);

    // ---- fused prologue ----
    prologue_k<<<(PR_TOTAL + 255) / 256, blk>>>(f_node, f_edge, tree_msg, W1, W2, W3, W4, W5);

    // ---- node_h(f16) = f_node @ W1 ----
    tgemm<0><<<gN, blk, SM_BYTES>>>(fn, B1, nullptr, nullptr,
                                    nullptr, nh, NN, 256, nullptr, nullptr, nullptr, nullptr, nullptr);
    // ---- base(f16) = f_edge @ W2 + node_h[src] + b1 ; am = relu ----
    tgemm<1><<<gE, blk, SM_BYTES>>>(fe, B2, nullptr, nullptr,
                                    nullptr, base, NE, 64, b1, nh, edge_src, nullptr, am);
    // ---- base[tree_tgt] += tree_msg @ W3 ; patch am ----
    tgemm<2><<<gT, blk, SM_BYTES>>>(tm, B3, nullptr, nullptr,
                                    nullptr, base, MT, 256, nullptr, nullptr, tree_tgt, nullptr, am);

    // ---- iter 1: y1(f16) = relu(base) @ W3 ; aggA = segsum(y1, dst) ----
    tgemm<3><<<gE, blk, SM_BYTES>>>(am, B3, nullptr, nullptr,
                                    nullptr, y, NE, 256, nullptr, nullptr, edge_dst, aggA, nullptr);
    combine_k<false><<<combGrid, blk>>>(base, aggA, y, edge_src, edge_dst, am, nullptr);

    // ---- iter 2: y2(f16) = msg2 @ W3 ; aggB = segsum(y2, dst) ----
    tgemm<3><<<gE, blk, SM_BYTES>>>(am, B3, nullptr, nullptr,
                                    nullptr, y, NE, 256, nullptr, nullptr, edge_dst, aggB, nullptr);
    // ---- iter 3 fused with readout reduce ----
    combine_k<true><<<combGrid, blk>>>(base, aggB, y, edge_src, edge_dst, nullptr, nodesum);

    // ---- fused readout: out = relu(f_node @ W4 + node_sum @ W5 + b2) ----
    conv_k<<<(NN * 32 + 255) / 256, blk>>>(nodesum, ns, NN * 32);
    tgemm<6><<<gN, blk, SM_BYTES>>>(fn, B4, ns, B5,
                                    out, nullptr, NN, 256, b2, nullptr, nullptr, nullptr, nullptr);
}

// round 16
// speedup vs baseline: 1.0197x; 1.0197x over previous
#include <cuda_runtime.h>
#include <cuda_fp16.h>
#include <cstdint>

#define NN 100000
#define NE 300000
#define MT 10000

typedef unsigned long long u64;
typedef unsigned int u32;

// ---------------- scratch (device globals; no allocation allowed) ----------------
__device__ __half g_nh     [(size_t)NN*256];   // node_h fp16
__device__ __half g_base   [(size_t)NE*256];   // fp16 intermediate
__device__ __half g_y      [(size_t)NE*256];   // fp16 intermediate
__device__ float  g_aggA   [(size_t)NN*256];
__device__ float  g_aggB   [(size_t)NN*256];
__device__ float  g_nodesum[(size_t)NN*256];
// single-fp16 A-side buffers
__device__ __half g_fn[(size_t)NN*256];
__device__ __half g_fe[(size_t)NE*64];
__device__ __half g_tm[(size_t)MT*256];
__device__ __half g_a [(size_t)NE*256];
__device__ __half g_ns[(size_t)NN*256];
// B matrices transposed, single fp16: B[n][k] = W[k][n]
__device__ __half g_B1[256*256];
__device__ __half g_B2[256*64];
__device__ __half g_B3[256*256];
__device__ __half g_B4[256*256];
__device__ __half g_B5[256*256];

// ---------------- helpers ----------------
__device__ __forceinline__ u32 smem_u32(const void* p) {
    u32 a; asm("{ .reg .u64 t; cvta.to.shared.u64 t, %1; cvt.u32.u64 %0, t; }" : "=r"(a) : "l"(p));
    return a;
}
__device__ __forceinline__ void cp16(u32 dst, const void* src) {
    asm volatile("cp.async.cg.shared.global [%0], [%1], 16;" :: "r"(dst), "l"(src));
}
__device__ __forceinline__ void red2(float* p, float a, float b) {
    asm volatile("red.global.add.v2.f32 [%0], {%1,%2};" :: "l"(p), "f"(a), "f"(b) : "memory");
}
__device__ __forceinline__ void red4(float* p, float a, float b, float c, float d) {
    asm volatile("red.global.add.v4.f32 [%0], {%1,%2,%3,%4};"
                 :: "l"(p), "f"(a), "f"(b), "f"(c), "f"(d) : "memory");
}
__device__ __forceinline__ void ldsm4(u32* r, u32 addr) {
    asm volatile("ldmatrix.sync.aligned.m8n8.x4.shared.b16 {%0,%1,%2,%3}, [%4];"
                 : "=r"(r[0]), "=r"(r[1]), "=r"(r[2]), "=r"(r[3]) : "r"(addr));
}
__device__ __forceinline__ void mma16816(float* d, const u32* a, const u32* b) {
    asm volatile("mma.sync.aligned.m16n8k16.row.col.f32.f16.f16.f32 "
                 "{%0,%1,%2,%3}, {%4,%5,%6,%7}, {%8,%9}, {%0,%1,%2,%3};"
                 : "+f"(d[0]), "+f"(d[1]), "+f"(d[2]), "+f"(d[3])
                 : "r"(a[0]), "r"(a[1]), "r"(a[2]), "r"(a[3]), "r"(b[0]), "r"(b[1]));
}
__device__ __forceinline__ u32 pack2(float x, float y) {
    __half2 h = __floats2half2_rn(x, y);
    return *(u32*)&h;
}
__device__ __forceinline__ float2 unpack2(u32 v) {
    __half2 h = *(__half2*)&v;
    return make_float2(__half2float(__low2half(h)), __half2float(__high2half(h)));
}
__device__ __forceinline__ void conv_store4(__half* hp, float4 v) {
    ((u32*)hp)[0] = pack2(v.x, v.y);
    ((u32*)hp)[1] = pack2(v.z, v.w);
}

// smem: 2 stages x [A | B], each buffer 128 rows x 80 bytes = 10240 B
#define BUF_BYTES 10240u
#define STAGE_BYTES (2u * BUF_BYTES)
#define SM_BYTES (2 * STAGE_BYTES)       // 40960

// ------------------- mma.sync GEMM: C[M,256] = A[M,K] @ W[K,256], BK=32 -------------------
// single fp16 term, fp32 accumulate. CTA tile 128x128, grid (2, tiles_m).
// MODE 0: hC(f16) = acc                                       (node_h)
// MODE 1: hC(f16) = acc + addmatH[gidx[r]] + bias ; rout = relu (fp16)
// MODE 2: hC[gidx[r]](f16) += acc ; rout patched
// MODE 3: hC(f16) = acc ; red agg[gidx[r]] += acc
// MODE 6: C(f32) = relu(A@B + A2@B2 + bias)                   (fused readout; 16 chunks)
template<int MODE>
__global__ __launch_bounds__(256, 2)
void tgemm(const __half* __restrict__ A, const __half* __restrict__ B,
           const __half* __restrict__ A2, const __half* __restrict__ B2,
           float* __restrict__ C, __half* __restrict__ hC, int M, int K,
           const float* __restrict__ bias, const __half* __restrict__ addmatH,
           const int* __restrict__ gidx, float* __restrict__ agg,
           __half* __restrict__ rout)
{
    extern __shared__ char smem[];
    const u32 sb = smem_u32(smem);
    const int tid  = threadIdx.x;
    const int lane = tid & 31, w = tid >> 5;
    const int wm = w >> 2, wn = w & 3;
    const int bm = blockIdx.y * 128;
    const int bn = blockIdx.x * 128;
    const int nchunks = (MODE == 6) ? 16 : (K >> 5);

    float acc[4][4][4];
    #pragma unroll
    for (int i = 0; i < 4; i++)
        #pragma unroll
        for (int j = 0; j < 4; j++)
            #pragma unroll
            for (int q = 0; q < 4; q++) acc[i][j][q] = 0.f;

    const int lr = tid >> 1;
    const int ch = (tid & 1) * 2;
    int growA = bm + lr; if (growA >= M) growA = M - 1;
    const u32 so = (u32)lr * 80u + (u32)ch * 16u;

    auto load_chunk = [&](int c, int s) {
        const __half *pA = A, *pB = B;
        int cc = c;
        if (MODE == 6 && c >= 8) { pA = A2; pB = B2; cc = c - 8; }
        const u32 base = sb + (u32)s * STAGE_BYTES;
        const size_t gbA = ((size_t)growA * K + cc * 32 + ch * 8) * 2;
        const size_t gbB = ((size_t)(bn + lr) * K + cc * 32 + ch * 8) * 2;
        cp16(base + so,                  (const char*)pA + gbA);
        cp16(base + so + 16,             (const char*)pA + gbA + 16);
        cp16(base + BUF_BYTES + so,      (const char*)pB + gbB);
        cp16(base + BUF_BYTES + so + 16, (const char*)pB + gbB + 16);
    };

    const u32 aAddr = (u32)(wm * 64 + (lane & 15)) * 80u + (u32)(lane >> 4) * 16u;
    const u32 bAddr = (u32)(wn * 32 + ((lane >> 4) << 3) + (lane & 7)) * 80u
                    + (u32)((lane >> 3) & 1) * 16u;

    load_chunk(0, 0);
    asm volatile("cp.async.commit_group;" ::: "memory");

    for (int c = 0; c < nchunks; c++) {
        const int s = c & 1;
        if (c + 1 < nchunks) {
            load_chunk(c + 1, (c + 1) & 1);
            asm volatile("cp.async.commit_group;" ::: "memory");
            asm volatile("cp.async.wait_group 1;" ::: "memory");
        } else {
            asm volatile("cp.async.wait_group 0;" ::: "memory");
        }
        __syncthreads();

        const u32 stage = sb + (u32)s * STAGE_BYTES;
        #pragma unroll
        for (int ks = 0; ks < 2; ks++) {
            u32 bfv[2][4];
            #pragma unroll
            for (int p = 0; p < 2; p++)
                ldsm4(bfv[p], stage + BUF_BYTES + bAddr + (u32)p * (16u * 80u) + (u32)ks * 32u);
            u32 af[4][4];
            #pragma unroll
            for (int mt = 0; mt < 4; mt++)
                ldsm4(af[mt], stage + aAddr + (u32)mt * (16u * 80u) + (u32)ks * 32u);
            #pragma unroll
            for (int mt = 0; mt < 4; mt++)
                #pragma unroll
                for (int nt = 0; nt < 4; nt++)
                    mma16816(acc[mt][nt], af[mt], &bfv[nt >> 1][(nt & 1) * 2]);
        }
        __syncthreads();
    }

    // ---------------- epilogue ----------------
    #pragma unroll
    for (int mt = 0; mt < 4; mt++) {
        #pragma unroll
        for (int half = 0; half < 2; half++) {
            const int r = bm + wm * 64 + mt * 16 + (lane >> 2) + half * 8;
            if (r >= M) continue;
            int g = 0;
            if (MODE == 1 || MODE == 2 || MODE == 3) g = __ldg(gidx + r);
            const size_t rowC = (size_t)r * 256;
            #pragma unroll
            for (int nt = 0; nt < 4; nt++) {
                const int c0 = bn + wn * 32 + nt * 8 + (lane & 3) * 2;
                float vx = acc[mt][nt][2 * half], vy = acc[mt][nt][2 * half + 1];
                if constexpr (MODE == 0) {
                    *(u32*)(hC + rowC + c0) = pack2(vx, vy);
                } else if constexpr (MODE == 1) {
                    const float2 ad = unpack2(__ldg((const u32*)(addmatH + (size_t)g * 256 + c0)));
                    const float2 bi = *(const float2*)(bias + c0);
                    vx += ad.x + bi.x; vy += ad.y + bi.y;
                    *(u32*)(hC + rowC + c0)   = pack2(vx, vy);
                    *(u32*)(rout + rowC + c0) = pack2(fmaxf(vx, 0.f), fmaxf(vy, 0.f));
                } else if constexpr (MODE == 2) {
                    const size_t rowG = (size_t)g * 256;
                    float2 bs = unpack2(*(u32*)(hC + rowG + c0));
                    bs.x += vx; bs.y += vy;
                    *(u32*)(hC + rowG + c0)   = pack2(bs.x, bs.y);
                    *(u32*)(rout + rowG + c0) = pack2(fmaxf(bs.x, 0.f), fmaxf(bs.y, 0.f));
                } else if constexpr (MODE == 3) {
                    *(u32*)(hC + rowC + c0) = pack2(vx, vy);
                    red2(agg + (size_t)g * 256 + c0, vx, vy);
                } else if constexpr (MODE == 6) {
                    const float2 bi = *(const float2*)(bias + c0);
                    *(float2*)(C + rowC + c0) =
                        make_float2(fmaxf(vx + bi.x, 0.f), fmaxf(vy + bi.y, 0.f));
                }
            }
        }
    }
}

// ---------------- fused prologue: zeros + input conversions + weight transposes ----------
#define PR_Z  (3 * NN * 64)
#define PR_FN (NN * 64)
#define PR_FE (NE * 16)
#define PR_TM (MT * 64)
#define PR_BULK (PR_Z + PR_FN + PR_FE + PR_TM)
#define PR_W  (65536 * 4 + 16384)
#define PR_TOTAL (PR_BULK + PR_W)

__global__ __launch_bounds__(256)
void prologue_k(const float* __restrict__ f_node, const float* __restrict__ f_edge,
                const float* __restrict__ tree_msg,
                const float* __restrict__ W1, const float* __restrict__ W2,
                const float* __restrict__ W3, const float* __restrict__ W4,
                const float* __restrict__ W5)
{
    int i = blockIdx.x * blockDim.x + threadIdx.x;
    if (i >= PR_TOTAL) return;
    if (i < PR_Z) {
        int j = i;
        float4* p;
        if (j < NN * 64) p = (float4*)g_aggA;
        else if (j < 2 * NN * 64) { p = (float4*)g_aggB; j -= NN * 64; }
        else { p = (float4*)g_nodesum; j -= 2 * NN * 64; }
        p[j] = make_float4(0.f, 0.f, 0.f, 0.f);
        return;
    }
    i -= PR_Z;
    if (i < PR_FN) {
        conv_store4(g_fn + (size_t)i * 4, ((const float4*)f_node)[i]);
        return;
    }
    i -= PR_FN;
    if (i < PR_FE) {
        conv_store4(g_fe + (size_t)i * 4, ((const float4*)f_edge)[i]);
        return;
    }
    i -= PR_FE;
    if (i < PR_TM) {
        conv_store4(g_tm + (size_t)i * 4, ((const float4*)tree_msg)[i]);
        return;
    }
    i -= PR_TM;
    const float* W; __half* h; int K;
    if (i < 65536)                { W = W1; h = g_B1; K = 256; }
    else if (i < 65536 + 16384)   { i -= 65536; W = W2; h = g_B2; K = 64; }
    else if (i < 2*65536 + 16384) { i -= 65536 + 16384; W = W3; h = g_B3; K = 256; }
    else if (i < 3*65536 + 16384) { i -= 2*65536 + 16384; W = W4; h = g_B4; K = 256; }
    else                          { i -= 3*65536 + 16384; W = W5; h = g_B5; K = 256; }
    int n = i / K, k = i % K;
    h[i] = __float2half_rn(W[(size_t)k * 256 + n]);
}

// ---------------- combine: m = relu(base + agg[src] - y[e^1]), 8 lanes/thread --------
template<bool FINAL>
__global__ __launch_bounds__(256)
void combine_k(const __half* __restrict__ base, const float* __restrict__ agg,
               const __half* __restrict__ y, const int* __restrict__ esrc,
               const int* __restrict__ edst,
               __half* __restrict__ mOut, float* __restrict__ nodesum)
{
    int gid = blockIdx.x * blockDim.x + threadIdx.x;
    if (gid >= NE * 32) return;
    int e = gid >> 5;
    int c = (gid & 31) << 3;
    int s = __ldg(esrc + e);
    uint4 bv = *(const uint4*)(base + (size_t)e * 256 + c);
    uint4 yv = *(const uint4*)(y + (size_t)(e ^ 1) * 256 + c);
    const float4* ap = (const float4*)(agg + (size_t)s * 256 + c);
    float4 a0 = ap[0], a1 = ap[1];
    float2 b0 = unpack2(bv.x), b1 = unpack2(bv.y), b2 = unpack2(bv.z), b3 = unpack2(bv.w);
    float2 z0 = unpack2(yv.x), z1 = unpack2(yv.y), z2 = unpack2(yv.z), z3 = unpack2(yv.w);
    float m0 = fmaxf(b0.x + a0.x - z0.x, 0.f);
    float m1 = fmaxf(b0.y + a0.y - z0.y, 0.f);
    float m2 = fmaxf(b1.x + a0.z - z1.x, 0.f);
    float m3 = fmaxf(b1.y + a0.w - z1.y, 0.f);
    float m4 = fmaxf(b2.x + a1.x - z2.x, 0.f);
    float m5 = fmaxf(b2.y + a1.y - z2.y, 0.f);
    float m6 = fmaxf(b3.x + a1.z - z3.x, 0.f);
    float m7 = fmaxf(b3.y + a1.w - z3.y, 0.f);
    if (FINAL) {
        int d = __ldg(edst + e);
        float* np = nodesum + (size_t)d * 256 + c;
        red4(np,     m0, m1, m2, m3);
        red4(np + 4, m4, m5, m6, m7);
    } else {
        uint4 hv;
        hv.x = pack2(m0, m1); hv.y = pack2(m2, m3);
        hv.z = pack2(m4, m5); hv.w = pack2(m6, m7);
        *(uint4*)(mOut + (size_t)e * 256 + c) = hv;
    }
}

// convert nodesum -> fp16, 8 elems/thread
__global__ void conv_k(const float* __restrict__ x, __half* __restrict__ h, int n8)
{
    int i = blockIdx.x * blockDim.x + threadIdx.x;
    if (i >= n8) return;
    const float4* xp = (const float4*)(x + (size_t)i * 8);
    float4 v0 = xp[0], v1 = xp[1];
    uint4 hv;
    hv.x = pack2(v0.x, v0.y); hv.y = pack2(v0.z, v0.w);
    hv.z = pack2(v1.x, v1.y); hv.w = pack2(v1.z, v1.w);
    *(uint4*)(h + (size_t)i * 8) = hv;
}

// --------------------------------- launch ---------------------------------
extern "C" void kernel_launch(void* const* d_in, const int* in_sizes, int n_in,
                              void* d_out, int out_size)
{
    const float* f_node   = (const float*)d_in[0];
    const float* f_edge   = (const float*)d_in[1];
    const float* tree_msg = (const float*)d_in[2];
    const float* W1       = (const float*)d_in[3];
    const float* W2       = (const float*)d_in[4];
    const float* W3       = (const float*)d_in[5];
    const float* b1       = (const float*)d_in[6];
    const float* W4       = (const float*)d_in[7];
    const float* W5       = (const float*)d_in[8];
    const float* b2       = (const float*)d_in[9];
    const int* edge_src   = (const int*)d_in[10];
    const int* edge_dst   = (const int*)d_in[11];
    const int* tree_tgt   = (const int*)d_in[12];
    float* out = (float*)d_out;

    float *aggA, *aggB, *nodesum;
    __half *nh, *base, *y, *fn, *fe, *tm, *am, *ns, *B1, *B2, *B3, *B4, *B5;
    cudaGetSymbolAddress((void**)&nh,      g_nh);
    cudaGetSymbolAddress((void**)&base,    g_base);
    cudaGetSymbolAddress((void**)&y,       g_y);
    cudaGetSymbolAddress((void**)&aggA,    g_aggA);
    cudaGetSymbolAddress((void**)&aggB,    g_aggB);
    cudaGetSymbolAddress((void**)&nodesum, g_nodesum);
    cudaGetSymbolAddress((void**)&fn, g_fn);
    cudaGetSymbolAddress((void**)&fe, g_fe);
    cudaGetSymbolAddress((void**)&tm, g_tm);
    cudaGetSymbolAddress((void**)&am, g_a);
    cudaGetSymbolAddress((void**)&ns, g_ns);
    cudaGetSymbolAddress((void**)&B1, g_B1);
    cudaGetSymbolAddress((void**)&B2, g_B2);
    cudaGetSymbolAddress((void**)&B3, g_B3);
    cudaGetSymbolAddress((void**)&B4, g_B4);
    cudaGetSymbolAddress((void**)&B5, g_B5);

    cudaFuncSetAttribute(tgemm<0>, cudaFuncAttributeMaxDynamicSharedMemorySize, SM_BYTES);
    cudaFuncSetAttribute(tgemm<1>, cudaFuncAttributeMaxDynamicSharedMemorySize, SM_BYTES);
    cudaFuncSetAttribute(tgemm<2>, cudaFuncAttributeMaxDynamicSharedMemorySize, SM_BYTES);
    cudaFuncSetAttribute(tgemm<3>, cudaFuncAttributeMaxDynamicSharedMemorySize, SM_BYTES);
    cudaFuncSetAttribute(tgemm<6>, cudaFuncAttributeMaxDynamicSharedMemorySize, SM_BYTES);

    const dim3 blk(256);
    const int combGrid = (NE * 32 + 255) / 256;
    const dim3 gN(2, (NN + 127) / 128);
    const dim3 gE(2, (NE + 127) / 128);
    const dim3 gT(2, (MT + 127) / 128);

    // ---- fused prologue ----
    prologue_k<<<(PR_TOTAL + 255) / 256, blk>>>(f_node, f_edge, tree_msg, W1, W2, W3, W4, W5);

    // ---- node_h(f16) = f_node @ W1 ----
    tgemm<0><<<gN, blk, SM_BYTES>>>(fn, B1, nullptr, nullptr,
                                    nullptr, nh, NN, 256, nullptr, nullptr, nullptr, nullptr, nullptr);
    // ---- base(f16) = f_edge @ W2 + node_h[src] + b1 ; am = relu ----
    tgemm<1><<<gE, blk, SM_BYTES>>>(fe, B2, nullptr, nullptr,
                                    nullptr, base, NE, 64, b1, nh, edge_src, nullptr, am);
    // ---- base[tree_tgt] += tree_msg @ W3 ; patch am ----
    tgemm<2><<<gT, blk, SM_BYTES>>>(tm, B3, nullptr, nullptr,
                                    nullptr, base, MT, 256, nullptr, nullptr, tree_tgt, nullptr, am);

    // ---- iter 1: y1(f16) = relu(base) @ W3 ; aggA = segsum(y1, dst) ----
    tgemm<3><<<gE, blk, SM_BYTES>>>(am, B3, nullptr, nullptr,
                                    nullptr, y, NE, 256, nullptr, nullptr, edge_dst, aggA, nullptr);
    combine_k<false><<<combGrid, blk>>>(base, aggA, y, edge_src, edge_dst, am, nullptr);

    // ---- iter 2: y2(f16) = msg2 @ W3 ; aggB = segsum(y2, dst) ----
    tgemm<3><<<gE, blk, SM_BYTES>>>(am, B3, nullptr, nullptr,
                                    nullptr, y, NE, 256, nullptr, nullptr, edge_dst, aggB, nullptr);
    // ---- iter 3 fused with readout reduce ----
    combine_k<true><<<combGrid, blk>>>(base, aggB, y, edge_src, edge_dst, nullptr, nodesum);

    // ---- fused readout: out = relu(f_node @ W4 + node_sum @ W5 + b2) ----
    conv_k<<<(NN * 32 + 255) / 256, blk>>>(nodesum, ns, NN * 32);
    tgemm<6><<<gN, blk, SM_BYTES>>>(fn, B4, ns, B5,
                                    out, nullptr, NN, 256, b2, nullptr, nullptr, nullptr, nullptr);
}

// round 17
// speedup vs baseline: 1.0500x; 1.0297x over previous
#include <cuda_runtime.h>
#include <cuda_fp16.h>
#include <cstdint>

#define NN 100000
#define NE 300000
#define MT 10000

typedef unsigned long long u64;
typedef unsigned int u32;

// ---------------- scratch (device globals; no allocation allowed) ----------------
__device__ __half g_nh     [(size_t)NN*256];   // node_h fp16
__device__ __half g_base   [(size_t)NE*256];   // fp16 intermediate
__device__ __half g_y      [(size_t)NE*256];   // fp16 intermediate
__device__ __half g_alpha  [(size_t)MT*256];   // tree_msg @ W3, fp16
__device__ int    g_itree  [NE];               // 0 = no tree msg, else row+1
__device__ float  g_aggA   [(size_t)NN*256];
__device__ float  g_aggB   [(size_t)NN*256];
__device__ float  g_nodesum[(size_t)NN*256];
// single-fp16 A-side buffers
__device__ __half g_fn[(size_t)NN*256];
__device__ __half g_fe[(size_t)NE*64];
__device__ __half g_tm[(size_t)MT*256];
__device__ __half g_a [(size_t)NE*256];
__device__ __half g_ns[(size_t)NN*256];
// B matrices transposed, single fp16: B[n][k] = W[k][n]
__device__ __half g_B1[256*256];
__device__ __half g_B2[256*64];
__device__ __half g_B3[256*256];
__device__ __half g_B4[256*256];
__device__ __half g_B5[256*256];

// ---------------- helpers ----------------
__device__ __forceinline__ u32 smem_u32(const void* p) {
    u32 a; asm("{ .reg .u64 t; cvta.to.shared.u64 t, %1; cvt.u32.u64 %0, t; }" : "=r"(a) : "l"(p));
    return a;
}
__device__ __forceinline__ void cp16(u32 dst, const void* src) {
    asm volatile("cp.async.cg.shared.global [%0], [%1], 16;" :: "r"(dst), "l"(src));
}
__device__ __forceinline__ void red2(float* p, float a, float b) {
    asm volatile("red.global.add.v2.f32 [%0], {%1,%2};" :: "l"(p), "f"(a), "f"(b) : "memory");
}
__device__ __forceinline__ void red4(float* p, float a, float b, float c, float d) {
    asm volatile("red.global.add.v4.f32 [%0], {%1,%2,%3,%4};"
                 :: "l"(p), "f"(a), "f"(b), "f"(c), "f"(d) : "memory");
}
__device__ __forceinline__ void ldsm4(u32* r, u32 addr) {
    asm volatile("ldmatrix.sync.aligned.m8n8.x4.shared.b16 {%0,%1,%2,%3}, [%4];"
                 : "=r"(r[0]), "=r"(r[1]), "=r"(r[2]), "=r"(r[3]) : "r"(addr));
}
__device__ __forceinline__ void mma16816(float* d, const u32* a, const u32* b) {
    asm volatile("mma.sync.aligned.m16n8k16.row.col.f32.f16.f16.f32 "
                 "{%0,%1,%2,%3}, {%4,%5,%6,%7}, {%8,%9}, {%0,%1,%2,%3};"
                 : "+f"(d[0]), "+f"(d[1]), "+f"(d[2]), "+f"(d[3])
                 : "r"(a[0]), "r"(a[1]), "r"(a[2]), "r"(a[3]), "r"(b[0]), "r"(b[1]));
}
__device__ __forceinline__ u32 pack2(float x, float y) {
    __half2 h = __floats2half2_rn(x, y);
    return *(u32*)&h;
}
__device__ __forceinline__ float2 unpack2(u32 v) {
    __half2 h = *(__half2*)&v;
    return make_float2(__half2float(__low2half(h)), __half2float(__high2half(h)));
}
__device__ __forceinline__ void conv_store4(__half* hp, float4 v) {
    ((u32*)hp)[0] = pack2(v.x, v.y);
    ((u32*)hp)[1] = pack2(v.z, v.w);
}

// smem: 2 stages x [A | B], each buffer 128 rows x 80 bytes = 10240 B
#define BUF_BYTES 10240u
#define STAGE_BYTES (2u * BUF_BYTES)
#define SM_BYTES (2 * STAGE_BYTES)       // 40960

// ------------------- mma.sync GEMM: C[M,256] = A[M,K] @ W[K,256], BK=32 -------------------
// single fp16 term, fp32 accumulate. CTA tile 128x128, grid (2, tiles_m).
// MODE 0: hC(f16) = acc                                       (node_h / alpha)
// MODE 1: hC(f16) = acc + addmatH[gidx[r]] + bias + alpha[itree[r]-1] ; rout = relu (fp16)
// MODE 3: hC(f16) = acc ; red agg[gidx[r]] += acc
// MODE 6: C(f32) = relu(A@B + A2@B2 + bias)                   (fused readout; 16 chunks)
template<int MODE>
__global__ __launch_bounds__(256, 2)
void tgemm(const __half* __restrict__ A, const __half* __restrict__ B,
           const __half* __restrict__ A2, const __half* __restrict__ B2,
           float* __restrict__ C, __half* __restrict__ hC, int M, int K,
           const float* __restrict__ bias, const __half* __restrict__ addmatH,
           const int* __restrict__ gidx, float* __restrict__ agg,
           __half* __restrict__ rout,
           const __half* __restrict__ alphaH, const int* __restrict__ itree)
{
    extern __shared__ char smem[];
    const u32 sb = smem_u32(smem);
    const int tid  = threadIdx.x;
    const int lane = tid & 31, w = tid >> 5;
    const int wm = w >> 2, wn = w & 3;
    const int bm = blockIdx.y * 128;
    const int bn = blockIdx.x * 128;
    const int nchunks = (MODE == 6) ? 16 : (K >> 5);

    float acc[4][4][4];
    #pragma unroll
    for (int i = 0; i < 4; i++)
        #pragma unroll
        for (int j = 0; j < 4; j++)
            #pragma unroll
            for (int q = 0; q < 4; q++) acc[i][j][q] = 0.f;

    const int lr = tid >> 1;
    const int ch = (tid & 1) * 2;
    int growA = bm + lr; if (growA >= M) growA = M - 1;
    const u32 so = (u32)lr * 80u + (u32)ch * 16u;

    auto load_chunk = [&](int c, int s) {
        const __half *pA = A, *pB = B;
        int cc = c;
        if (MODE == 6 && c >= 8) { pA = A2; pB = B2; cc = c - 8; }
        const u32 base = sb + (u32)s * STAGE_BYTES;
        const size_t gbA = ((size_t)growA * K + cc * 32 + ch * 8) * 2;
        const size_t gbB = ((size_t)(bn + lr) * K + cc * 32 + ch * 8) * 2;
        cp16(base + so,                  (const char*)pA + gbA);
        cp16(base + so + 16,             (const char*)pA + gbA + 16);
        cp16(base + BUF_BYTES + so,      (const char*)pB + gbB);
        cp16(base + BUF_BYTES + so + 16, (const char*)pB + gbB + 16);
    };

    const u32 aAddr = (u32)(wm * 64 + (lane & 15)) * 80u + (u32)(lane >> 4) * 16u;
    const u32 bAddr = (u32)(wn * 32 + ((lane >> 4) << 3) + (lane & 7)) * 80u
                    + (u32)((lane >> 3) & 1) * 16u;

    load_chunk(0, 0);
    asm volatile("cp.async.commit_group;" ::: "memory");

    for (int c = 0; c < nchunks; c++) {
        const int s = c & 1;
        if (c + 1 < nchunks) {
            load_chunk(c + 1, (c + 1) & 1);
            asm volatile("cp.async.commit_group;" ::: "memory");
            asm volatile("cp.async.wait_group 1;" ::: "memory");
        } else {
            asm volatile("cp.async.wait_group 0;" ::: "memory");
        }
        __syncthreads();

        const u32 stage = sb + (u32)s * STAGE_BYTES;
        #pragma unroll
        for (int ks = 0; ks < 2; ks++) {
            u32 bfv[2][4];
            #pragma unroll
            for (int p = 0; p < 2; p++)
                ldsm4(bfv[p], stage + BUF_BYTES + bAddr + (u32)p * (16u * 80u) + (u32)ks * 32u);
            u32 af[4][4];
            #pragma unroll
            for (int mt = 0; mt < 4; mt++)
                ldsm4(af[mt], stage + aAddr + (u32)mt * (16u * 80u) + (u32)ks * 32u);
            #pragma unroll
            for (int mt = 0; mt < 4; mt++)
                #pragma unroll
                for (int nt = 0; nt < 4; nt++)
                    mma16816(acc[mt][nt], af[mt], &bfv[nt >> 1][(nt & 1) * 2]);
        }
        __syncthreads();
    }

    // ---------------- epilogue ----------------
    #pragma unroll
    for (int mt = 0; mt < 4; mt++) {
        #pragma unroll
        for (int half = 0; half < 2; half++) {
            const int r = bm + wm * 64 + mt * 16 + (lane >> 2) + half * 8;
            if (r >= M) continue;
            int g = 0, ti = 0;
            if (MODE == 1 || MODE == 3) g = __ldg(gidx + r);
            if (MODE == 1) ti = __ldg(itree + r);
            const size_t rowC = (size_t)r * 256;
            #pragma unroll
            for (int nt = 0; nt < 4; nt++) {
                const int c0 = bn + wn * 32 + nt * 8 + (lane & 3) * 2;
                float vx = acc[mt][nt][2 * half], vy = acc[mt][nt][2 * half + 1];
                if constexpr (MODE == 0) {
                    *(u32*)(hC + rowC + c0) = pack2(vx, vy);
                } else if constexpr (MODE == 1) {
                    const float2 ad = unpack2(__ldg((const u32*)(addmatH + (size_t)g * 256 + c0)));
                    const float2 bi = *(const float2*)(bias + c0);
                    vx += ad.x + bi.x; vy += ad.y + bi.y;
                    if (ti > 0) {
                        const float2 av =
                            unpack2(__ldg((const u32*)(alphaH + (size_t)(ti - 1) * 256 + c0)));
                        vx += av.x; vy += av.y;
                    }
                    *(u32*)(hC + rowC + c0)   = pack2(vx, vy);
                    *(u32*)(rout + rowC + c0) = pack2(fmaxf(vx, 0.f), fmaxf(vy, 0.f));
                } else if constexpr (MODE == 3) {
                    *(u32*)(hC + rowC + c0) = pack2(vx, vy);
                    red2(agg + (size_t)g * 256 + c0, vx, vy);
                } else if constexpr (MODE == 6) {
                    const float2 bi = *(const float2*)(bias + c0);
                    *(float2*)(C + rowC + c0) =
                        make_float2(fmaxf(vx + bi.x, 0.f), fmaxf(vy + bi.y, 0.f));
                }
            }
        }
    }
}

// ---------------- fused prologue: zeros + conversions + weight transposes + itree scatter --
#define PR_Z  (3 * NN * 64)
#define PR_FN (NN * 64)
#define PR_FE (NE * 16)
#define PR_TM (MT * 64)
#define PR_TT MT
#define PR_BULK (PR_Z + PR_FN + PR_FE + PR_TM + PR_TT)
#define PR_W  (65536 * 4 + 16384)
#define PR_TOTAL (PR_BULK + PR_W)

__global__ __launch_bounds__(256)
void prologue_k(const float* __restrict__ f_node, const float* __restrict__ f_edge,
                const float* __restrict__ tree_msg, const int* __restrict__ tree_tgt,
                const float* __restrict__ W1, const float* __restrict__ W2,
                const float* __restrict__ W3, const float* __restrict__ W4,
                const float* __restrict__ W5)
{
    int i = blockIdx.x * blockDim.x + threadIdx.x;
    if (i >= PR_TOTAL) return;
    if (i < PR_Z) {
        int j = i;
        float4* p;
        if (j < NN * 64) p = (float4*)g_aggA;
        else if (j < 2 * NN * 64) { p = (float4*)g_aggB; j -= NN * 64; }
        else { p = (float4*)g_nodesum; j -= 2 * NN * 64; }
        p[j] = make_float4(0.f, 0.f, 0.f, 0.f);
        return;
    }
    i -= PR_Z;
    if (i < PR_FN) {
        conv_store4(g_fn + (size_t)i * 4, ((const float4*)f_node)[i]);
        return;
    }
    i -= PR_FN;
    if (i < PR_FE) {
        conv_store4(g_fe + (size_t)i * 4, ((const float4*)f_edge)[i]);
        return;
    }
    i -= PR_FE;
    if (i < PR_TM) {
        conv_store4(g_tm + (size_t)i * 4, ((const float4*)tree_msg)[i]);
        return;
    }
    i -= PR_TM;
    if (i < PR_TT) {
        // non-target entries of g_itree stay 0 from static zero-init; targets get the
        // same value on every call -> deterministic across graph replays.
        g_itree[__ldg(tree_tgt + i)] = i + 1;
        return;
    }
    i -= PR_TT;
    const float* W; __half* h; int K;
    if (i < 65536)                { W = W1; h = g_B1; K = 256; }
    else if (i < 65536 + 16384)   { i -= 65536; W = W2; h = g_B2; K = 64; }
    else if (i < 2*65536 + 16384) { i -= 65536 + 16384; W = W3; h = g_B3; K = 256; }
    else if (i < 3*65536 + 16384) { i -= 2*65536 + 16384; W = W4; h = g_B4; K = 256; }
    else                          { i -= 3*65536 + 16384; W = W5; h = g_B5; K = 256; }
    int n = i / K, k = i % K;
    h[i] = __float2half_rn(W[(size_t)k * 256 + n]);
}

// ---------------- combine: m = relu(base + agg[src] - y[e^1]), 8 lanes/thread --------
template<bool FINAL>
__global__ __launch_bounds__(256)
void combine_k(const __half* __restrict__ base, const float* __restrict__ agg,
               const __half* __restrict__ y, const int* __restrict__ esrc,
               const int* __restrict__ edst,
               __half* __restrict__ mOut, float* __restrict__ nodesum)
{
    int gid = blockIdx.x * blockDim.x + threadIdx.x;
    if (gid >= NE * 32) return;
    int e = gid >> 5;
    int c = (gid & 31) << 3;
    int s = __ldg(esrc + e);
    uint4 bv = *(const uint4*)(base + (size_t)e * 256 + c);
    uint4 yv = *(const uint4*)(y + (size_t)(e ^ 1) * 256 + c);
    const float4* ap = (const float4*)(agg + (size_t)s * 256 + c);
    float4 a0 = ap[0], a1 = ap[1];
    float2 b0 = unpack2(bv.x), b1 = unpack2(bv.y), b2 = unpack2(bv.z), b3 = unpack2(bv.w);
    float2 z0 = unpack2(yv.x), z1 = unpack2(yv.y), z2 = unpack2(yv.z), z3 = unpack2(yv.w);
    float m0 = fmaxf(b0.x + a0.x - z0.x, 0.f);
    float m1 = fmaxf(b0.y + a0.y - z0.y, 0.f);
    float m2 = fmaxf(b1.x + a0.z - z1.x, 0.f);
    float m3 = fmaxf(b1.y + a0.w - z1.y, 0.f);
    float m4 = fmaxf(b2.x + a1.x - z2.x, 0.f);
    float m5 = fmaxf(b2.y + a1.y - z2.y, 0.f);
    float m6 = fmaxf(b3.x + a1.z - z3.x, 0.f);
    float m7 = fmaxf(b3.y + a1.w - z3.y, 0.f);
    if (FINAL) {
        int d = __ldg(edst + e);
        float* np = nodesum + (size_t)d * 256 + c;
        red4(np,     m0, m1, m2, m3);
        red4(np + 4, m4, m5, m6, m7);
    } else {
        uint4 hv;
        hv.x = pack2(m0, m1); hv.y = pack2(m2, m3);
        hv.z = pack2(m4, m5); hv.w = pack2(m6, m7);
        *(uint4*)(mOut + (size_t)e * 256 + c) = hv;
    }
}

// convert nodesum -> fp16, 8 elems/thread
__global__ void conv_k(const float* __restrict__ x, __half* __restrict__ h, int n8)
{
    int i = blockIdx.x * blockDim.x + threadIdx.x;
    if (i >= n8) return;
    const float4* xp = (const float4*)(x + (size_t)i * 8);
    float4 v0 = xp[0], v1 = xp[1];
    uint4 hv;
    hv.x = pack2(v0.x, v0.y); hv.y = pack2(v0.z, v0.w);
    hv.z = pack2(v1.x, v1.y); hv.w = pack2(v1.z, v1.w);
    *(uint4*)(h + (size_t)i * 8) = hv;
}

// --------------------------------- launch ---------------------------------
extern "C" void kernel_launch(void* const* d_in, const int* in_sizes, int n_in,
                              void* d_out, int out_size)
{
    const float* f_node   = (const float*)d_in[0];
    const float* f_edge   = (const float*)d_in[1];
    const float* tree_msg = (const float*)d_in[2];
    const float* W1       = (const float*)d_in[3];
    const float* W2       = (const float*)d_in[4];
    const float* W3       = (const float*)d_in[5];
    const float* b1       = (const float*)d_in[6];
    const float* W4       = (const float*)d_in[7];
    const float* W5       = (const float*)d_in[8];
    const float* b2       = (const float*)d_in[9];
    const int* edge_src   = (const int*)d_in[10];
    const int* edge_dst   = (const int*)d_in[11];
    const int* tree_tgt   = (const int*)d_in[12];
    float* out = (float*)d_out;

    float *aggA, *aggB, *nodesum;
    int *itree;
    __half *nh, *base, *y, *alpha, *fn, *fe, *tm, *am, *ns, *B1, *B2, *B3, *B4, *B5;
    cudaGetSymbolAddress((void**)&nh,      g_nh);
    cudaGetSymbolAddress((void**)&base,    g_base);
    cudaGetSymbolAddress((void**)&y,       g_y);
    cudaGetSymbolAddress((void**)&alpha,   g_alpha);
    cudaGetSymbolAddress((void**)&itree,   g_itree);
    cudaGetSymbolAddress((void**)&aggA,    g_aggA);
    cudaGetSymbolAddress((void**)&aggB,    g_aggB);
    cudaGetSymbolAddress((void**)&nodesum, g_nodesum);
    cudaGetSymbolAddress((void**)&fn, g_fn);
    cudaGetSymbolAddress((void**)&fe, g_fe);
    cudaGetSymbolAddress((void**)&tm, g_tm);
    cudaGetSymbolAddress((void**)&am, g_a);
    cudaGetSymbolAddress((void**)&ns, g_ns);
    cudaGetSymbolAddress((void**)&B1, g_B1);
    cudaGetSymbolAddress((void**)&B2, g_B2);
    cudaGetSymbolAddress((void**)&B3, g_B3);
    cudaGetSymbolAddress((void**)&B4, g_B4);
    cudaGetSymbolAddress((void**)&B5, g_B5);

    cudaFuncSetAttribute(tgemm<0>, cudaFuncAttributeMaxDynamicSharedMemorySize, SM_BYTES);
    cudaFuncSetAttribute(tgemm<1>, cudaFuncAttributeMaxDynamicSharedMemorySize, SM_BYTES);
    cudaFuncSetAttribute(tgemm<3>, cudaFuncAttributeMaxDynamicSharedMemorySize, SM_BYTES);
    cudaFuncSetAttribute(tgemm<6>, cudaFuncAttributeMaxDynamicSharedMemorySize, SM_BYTES);

    const dim3 blk(256);
    const int combGrid = (NE * 32 + 255) / 256;
    const dim3 gN(2, (NN + 127) / 128);
    const dim3 gE(2, (NE + 127) / 128);
    const dim3 gT(2, (MT + 127) / 128);

    // ---- fused prologue (includes itree scatter) ----
    prologue_k<<<(PR_TOTAL + 255) / 256, blk>>>(f_node, f_edge, tree_msg, tree_tgt,
                                                W1, W2, W3, W4, W5);

    // ---- alpha(f16) = tree_msg @ W3 (dense store; replaces the RMW tree patch) ----
    tgemm<0><<<gT, blk, SM_BYTES>>>(tm, B3, nullptr, nullptr,
                                    nullptr, alpha, MT, 256, nullptr, nullptr, nullptr,
                                    nullptr, nullptr, nullptr, nullptr);
    // ---- node_h(f16) = f_node @ W1 ----
    tgemm<0><<<gN, blk, SM_BYTES>>>(fn, B1, nullptr, nullptr,
                                    nullptr, nh, NN, 256, nullptr, nullptr, nullptr,
                                    nullptr, nullptr, nullptr, nullptr);
    // ---- base(f16) = f_edge @ W2 + node_h[src] + b1 + alpha[itree] ; am = relu ----
    tgemm<1><<<gE, blk, SM_BYTES>>>(fe, B2, nullptr, nullptr,
                                    nullptr, base, NE, 64, b1, nh, edge_src,
                                    nullptr, am, alpha, itree);

    // ---- iter 1: y1(f16) = relu(base) @ W3 ; aggA = segsum(y1, dst) ----
    tgemm<3><<<gE, blk, SM_BYTES>>>(am, B3, nullptr, nullptr,
                                    nullptr, y, NE, 256, nullptr, nullptr, edge_dst,
                                    aggA, nullptr, nullptr, nullptr);
    combine_k<false><<<combGrid, blk>>>(base, aggA, y, edge_src, edge_dst, am, nullptr);

    // ---- iter 2: y2(f16) = msg2 @ W3 ; aggB = segsum(y2, dst) ----
    tgemm<3><<<gE, blk, SM_BYTES>>>(am, B3, nullptr, nullptr,
                                    nullptr, y, NE, 256, nullptr, nullptr, edge_dst,
                                    aggB, nullptr, nullptr, nullptr);
    // ---- iter 3 fused with readout reduce ----
    combine_k<true><<<combGrid, blk>>>(base, aggB, y, edge_src, edge_dst, nullptr, nodesum);

    // ---- fused readout: out = relu(f_node @ W4 + node_sum @ W5 + b2) ----
    conv_k<<<(NN * 32 + 255) / 256, blk>>>(nodesum, ns, NN * 32);
    tgemm<6><<<gN, blk, SM_BYTES>>>(fn, B4, ns, B5,
                                    out, nullptr, NN, 256, b2, nullptr, nullptr,
                                    nullptr, nullptr, nullptr, nullptr);
}